// round 4
// baseline (speedup 1.0000x reference)
#include <cuda_runtime.h>
#include <math.h>

#define NB   1024
#define NTOK 256
#define NV   200
#define BT   16

typedef unsigned long long u64;

// ---------------- device scratch ----------------
__device__ float g_udp[3][NB][NV];
__device__ float g_mean[3][NV];
__device__ float g_rstd[3][NV];

// ---------------- helpers ----------------
__device__ __forceinline__ float warp_sum(float v) {
#pragma unroll
    for (int o = 16; o; o >>= 1) v += __shfl_xor_sync(0xffffffffu, v, o);
    return v;
}
__device__ __forceinline__ float warp_max(float v) {
#pragma unroll
    for (int o = 16; o; o >>= 1) v = fmaxf(v, __shfl_xor_sync(0xffffffffu, v, o));
    return v;
}
__device__ __forceinline__ u64 ffma2(u64 a, u64 b, u64 c) {
    u64 d;
    asm("fma.rn.f32x2 %0, %1, %2, %3;" : "=l"(d) : "l"(a), "l"(b), "l"(c));
    return d;
}
union F2U { float2 f; u64 u; };
__device__ __forceinline__ u64 pack2(float x, float y) {
    F2U t; t.f = make_float2(x, y); return t.u;
}
__device__ __forceinline__ float2 unpack2(u64 v) { F2U t; t.u = v; return t.f; }

// ---------------- kernel 1: attention, block-per-batch, coalesced ----------------
__global__ __launch_bounds__(256) void k_attn(
    const float* __restrict__ merged, const float* __restrict__ a,
    const float* __restrict__ upWq, const float* __restrict__ upWk, const float* __restrict__ upWv,
    const float* __restrict__ dnWq, const float* __restrict__ dnWk, const float* __restrict__ dnWv,
    const float* __restrict__ pvWq, const float* __restrict__ pvWk, const float* __restrict__ pvWv,
    float* __restrict__ out)
{
    __shared__ float feat[NTOK * 15];
    __shared__ float sM[245];        // Mu[7][14] | Md[7][14] | Mp[7][7]
    __shared__ float sqk[35];        // qku[14] | qkd[14] | qkp[7]
    __shared__ float wred[8][6];
    __shared__ float wpart[8][38];
    __shared__ float sred[38];       // Su,Sd,Sp | wfu[14] | wfd[14] | wfp[7]

    int b = blockIdx.x, t = threadIdx.x;
    int wid = t >> 5, lane = t & 31;

    const float* src = merged + (size_t)b * NTOK * 15;
    for (int i = t; i < NTOK * 15; i += 256) feat[i] = src[i];
    if (b < 4) out[b * 256 + t] = 0.f;       // zero output once per replay

    if (t < 245) {                            // M = Wq @ Wk^T
        const float *Wq, *Wk; int j, f;
        if (t < 98)       { Wq = upWq; Wk = upWk; j = t / 14;        f = t % 14; }
        else if (t < 196) { Wq = dnWq; Wk = dnWk; j = (t - 98) / 14; f = (t - 98) % 14; }
        else              { Wq = pvWq; Wk = pvWk; j = (t - 196) / 7; f = (t - 196) % 7; }
        const float4* q4 = (const float4*)(Wq + j * NV);
        const float4* k4 = (const float4*)(Wk + f * NV);
        float s = 0.f;
#pragma unroll 5
        for (int v = 0; v < NV / 4; v++) {
            float4 qa = q4[v], ka = k4[v];
            s += qa.x * ka.x + qa.y * ka.y + qa.z * ka.z + qa.w * ka.w;
        }
        sM[t] = s;
    }
    float a_b = a[b];
    __syncthreads();

    float subj_id = feat[0], subj_loc = feat[2];
    if (t < 35) {                             // qk = M^T @ ego
        float ego[7];
        ego[0] = 0.f; ego[1] = feat[1]; ego[2] = feat[2]; ego[3] = feat[3];
        ego[4] = feat[4]; ego[5] = feat[5]; ego[6] = a_b;
        float s = 0.f;
        if (t < 14) {
#pragma unroll
            for (int j = 0; j < 7; j++) s += ego[j] * sM[j * 14 + t];
        } else if (t < 28) {
            int f = t - 14;
#pragma unroll
            for (int j = 0; j < 7; j++) s += ego[j] * sM[98 + j * 14 + f];
        } else {
            int f = t - 28;
#pragma unroll
            for (int j = 0; j < 7; j++) s += ego[j] * sM[196 + j * 7 + f];
        }
        sqk[t] = s;
    }
    __syncthreads();

    // per-thread token
    float f[15];
#pragma unroll
    for (int q = 0; q < 15; q++) f[q] = feat[t * 15 + q];
    f[0] -= subj_id; f[7] -= subj_id;
    if (t == 0) f[6] = a_b;

    float s1 = 0.f, s2 = 0.f, s3 = 0.f;
#pragma unroll
    for (int q = 0; q < 14; q++) { s1 = fmaf(f[q], sqk[q], s1); s2 = fmaf(f[q], sqk[14 + q], s2); }
#pragma unroll
    for (int q = 0; q < 7; q++)  s3 = fmaf(f[q], sqk[28 + q], s3);

    const float scale = 0.07071067811865475f;   // 1/sqrt(200)
    bool fl1  = (f[14] == 1.0f);
    bool m_up = (f[2] < subj_loc) && fl1;
    bool m_dn = (f[2] > subj_loc) && fl1;
    bool m_pv = (f[14] == 0.0f);
    float su = m_up ? s1 * scale : -1e9f;
    float sd = m_dn ? s2 * scale : -1e9f;
    float sp = m_pv ? s3 * scale : -1e9f;

    // round A: max + count
    float mu = warp_max(su), md = warp_max(sd), mp = warp_max(sp);
    float cu = warp_sum(m_up ? 1.f : 0.f);
    float cd = warp_sum(m_dn ? 1.f : 0.f);
    float cp = warp_sum(m_pv ? 1.f : 0.f);
    if (lane == 0) {
        wred[wid][0] = mu; wred[wid][1] = md; wred[wid][2] = mp;
        wred[wid][3] = cu; wred[wid][4] = cd; wred[wid][5] = cp;
    }
    __syncthreads();
    float BU = wred[0][0], BD = wred[0][1], BP = wred[0][2];
    float CU = wred[0][3], CD = wred[0][4], CP = wred[0][5];
#pragma unroll
    for (int w = 1; w < 8; w++) {
        BU = fmaxf(BU, wred[w][0]); BD = fmaxf(BD, wred[w][1]); BP = fmaxf(BP, wred[w][2]);
        CU += wred[w][3]; CD += wred[w][4]; CP += wred[w][5];
    }
    float eu = __expf(su - BU), ed = __expf(sd - BD), ep = __expf(sp - BP);

    // round B: 38 joint sums (Su,Sd,Sp + 35 weighted feature sums)
    float vals[38];
    vals[0] = eu; vals[1] = ed; vals[2] = ep;
#pragma unroll
    for (int q = 0; q < 14; q++) { vals[3 + q] = eu * f[q]; vals[17 + q] = ed * f[q]; }
#pragma unroll
    for (int q = 0; q < 7; q++)  vals[31 + q] = ep * f[q];
#pragma unroll
    for (int i = 0; i < 38; i++) {
        float v = warp_sum(vals[i]);
        if (lane == 0) wpart[wid][i] = v;
    }
    __syncthreads();
    if (t < 38) {
        float s = 0.f;
#pragma unroll
        for (int w = 0; w < 8; w++) s += wpart[w][t];
        sred[t] = s;
    }
    __syncthreads();

    // out = (wf / S) @ Wv
    if (t < NV) {
        float iSu = (CU > 0.5f) ? 1.f / sred[0] : 0.f;
        float iSd = (CD > 0.5f) ? 1.f / sred[1] : 0.f;
        float iSp = (CP > 0.5f) ? 1.f / sred[2] : 0.f;
        float ou = 0.f, od = 0.f, op = 0.f;
#pragma unroll
        for (int q = 0; q < 14; q++) {
            ou = fmaf(sred[3 + q],  __ldg(&upWv[q * NV + t]), ou);
            od = fmaf(sred[17 + q], __ldg(&dnWv[q * NV + t]), od);
        }
#pragma unroll
        for (int q = 0; q < 7; q++)
            op = fmaf(sred[31 + q], __ldg(&pvWv[q * NV + t]), op);
        g_udp[0][b][t] = ou * iSu;
        g_udp[1][b][t] = od * iSd;
        g_udp[2][b][t] = op * iSp;
    }
}

// ---------------- kernel 2: batch-norm stats ----------------
__global__ void k_stats() {
    int k  = blockIdx.y;
    int v  = blockIdx.x * 32 + threadIdx.x;
    int ty = threadIdx.y;           // 0..31
    double s = 0.0, s2 = 0.0;
    if (v < NV) {
        for (int b = ty; b < NB; b += 32) {
            float x = g_udp[k][b][v];
            s  += (double)x;
            s2 += (double)x * (double)x;
        }
    }
    __shared__ double ss[32][33], ss2[32][33];
    ss[ty][threadIdx.x]  = s;
    ss2[ty][threadIdx.x] = s2;
    __syncthreads();
    if (ty == 0 && v < NV) {
        for (int y = 1; y < 32; y++) { s += ss[y][threadIdx.x]; s2 += ss2[y][threadIdx.x]; }
        double mean = s / (double)NB;
        double var  = s2 / (double)NB - mean * mean;
        g_mean[k][v] = (float)mean;
        g_rstd[k][v] = (float)(1.0 / sqrt(var + 1e-5));
    }
}

// ---------------- kernel 3: 200x200 GEMMs, f32x2, direct-LDG W ----------------
// Block: BT=16 batches x 200 outputs. 256 threads.
// ty = t>>6 (0..3): 4 batches each; tx = t&63 (active < 50): 4 outputs.
// Per 2 k-steps: 2 LDG.128 (W) + 4 LDS.128 (X dup pairs) + 16 FFMA2.
__global__ __launch_bounds__(256) void k_mlp(const float* __restrict__ merged,
                                             const float* __restrict__ a,
                                             const float* __restrict__ tW1,
                                             const float* __restrict__ tb1,
                                             const float* __restrict__ tW2,
                                             const float* __restrict__ tb2,
                                             const float* __restrict__ eW1,
                                             const float* __restrict__ eb1,
                                             const float* __restrict__ eW2,
                                             const float* __restrict__ eb2,
                                             const float* __restrict__ eW3,
                                             const float* __restrict__ eb3,
                                             const float* __restrict__ gamma,
                                             const float* __restrict__ beta,
                                             float* __restrict__ out) {
    int unit = blockIdx.y;        // 0..2 heads, 3 = ego net
    int b0   = blockIdx.x * BT;
    int t    = threadIdx.x;
    int ty   = t >> 6;            // 0..3 (warp-uniform)
    int tx   = t & 63;            // active < 50
    bool act = tx < 50;

    __shared__ float2 Xd[BT][NV];   // duplicated activations (25600 B)

    // ---- build X (duplicated) ----
    if (unit < 3) {
        for (int i = t; i < BT * NV; i += 256) {
            int bb = i / NV, v = i - bb * NV;
            float x = g_udp[unit][b0 + bb][v];
            x = gamma[v] * (x - g_mean[unit][v]) * g_rstd[unit][v] + beta[v];
            Xd[bb][v] = make_float2(x, x);
        }
    } else if (t < NV) {
        float w0 = eW1[t], w1 = eW1[NV + t], w2 = eW1[2 * NV + t], w3 = eW1[3 * NV + t];
        float bb1 = eb1[t];
        for (int bb = 0; bb < BT; bb++) {
            const float* mr = merged + (size_t)(b0 + bb) * NTOK * 15;
            float h = fmaxf(mr[3] * w0 + mr[4] * w1 + mr[5] * w2 + a[b0 + bb] * w3 + bb1, 0.f);
            Xd[bb][t] = make_float2(h, h);
        }
    }
    __syncthreads();

    const float* Wg   = (unit < 3) ? tW1 + (size_t)unit * NV * NV : eW2;
    const float* bias = (unit < 3) ? tb1 + unit * NV : eb2;

    int o0 = tx * 4;
    u64 acc[4][2];
    if (act) {
        acc[0][0] = pack2(bias[o0], bias[o0 + 1]);
        acc[0][1] = pack2(bias[o0 + 2], bias[o0 + 3]);
#pragma unroll
        for (int i = 1; i < 4; i++) { acc[i][0] = acc[0][0]; acc[i][1] = acc[0][1]; }

#pragma unroll 4
        for (int k = 0; k < NV; k += 2) {
            ulonglong2 w0 = __ldg((const ulonglong2*)(Wg + (size_t)k * NV + o0));
            ulonglong2 w1 = __ldg((const ulonglong2*)(Wg + (size_t)(k + 1) * NV + o0));
#pragma unroll
            for (int i = 0; i < 4; i++) {
                ulonglong2 x = *reinterpret_cast<const ulonglong2*>(&Xd[ty * 4 + i][k]);
                acc[i][0] = ffma2(x.x, w0.x, acc[i][0]);
                acc[i][1] = ffma2(x.x, w0.y, acc[i][1]);
                acc[i][0] = ffma2(x.y, w1.x, acc[i][0]);
                acc[i][1] = ffma2(x.y, w1.y, acc[i][1]);
            }
        }
    }

    // ---- epilogue: activation, *W2, reduce ----
    float p[4] = {0.f, 0.f, 0.f, 0.f};
    if (act) {
        float w2v[4];
#pragma unroll
        for (int j = 0; j < 4; j++)
            w2v[j] = (unit < 3) ? tW2[unit * NV + o0 + j] : eW3[o0 + j];
#pragma unroll
        for (int i = 0; i < 4; i++) {
            float2 v01 = unpack2(acc[i][0]);
            float2 v23 = unpack2(acc[i][1]);
            float v[4] = {v01.x, v01.y, v23.x, v23.y};
            float s = 0.f;
#pragma unroll
            for (int j = 0; j < 4; j++) {
                float x = v[j];
                x = (unit < 3) ? (x > 0.f ? x : expm1f(x)) : fmaxf(x, 0.f);
                s = fmaf(x, w2v[j], s);
            }
            p[i] = s;
        }
    }
    __syncthreads();                       // done reading Xd
    float* red = (float*)&Xd[0][0];        // red[50][17]
    if (act) {
#pragma unroll
        for (int i = 0; i < 4; i++) red[tx * 17 + ty * 4 + i] = p[i];
    }
    __syncthreads();
    if (t < BT) {
        float s = 0.f;
        for (int j = 0; j < 50; j++) s += red[j * 17 + t];
        float fb = (unit < 3) ? tb2[unit] : eb3[0];
        atomicAdd(&out[b0 + t], s + fb);
    }
}

// ---------------- launch ----------------
extern "C" void kernel_launch(void* const* d_in, const int* in_sizes, int n_in,
                              void* d_out, int out_size) {
    (void)in_sizes; (void)n_in; (void)out_size;
    const float* merged = (const float*)d_in[0];
    const float* a      = (const float*)d_in[1];
    const float* upWq   = (const float*)d_in[2];
    const float* upWk   = (const float*)d_in[3];
    const float* upWv   = (const float*)d_in[4];
    const float* dnWq   = (const float*)d_in[5];
    const float* dnWk   = (const float*)d_in[6];
    const float* dnWv   = (const float*)d_in[7];
    const float* pvWq   = (const float*)d_in[8];
    const float* pvWk   = (const float*)d_in[9];
    const float* pvWv   = (const float*)d_in[10];
    const float* tW1    = (const float*)d_in[11];
    const float* tb1    = (const float*)d_in[12];
    const float* tW2    = (const float*)d_in[13];
    const float* tb2    = (const float*)d_in[14];
    const float* eW1    = (const float*)d_in[15];
    const float* eb1    = (const float*)d_in[16];
    const float* eW2    = (const float*)d_in[17];
    const float* eb2    = (const float*)d_in[18];
    const float* eW3    = (const float*)d_in[19];
    const float* eb3    = (const float*)d_in[20];
    const float* gamma  = (const float*)d_in[21];
    const float* beta   = (const float*)d_in[22];
    float* out = (float*)d_out;

    k_attn<<<NB, 256>>>(merged, a, upWq, upWk, upWv, dnWq, dnWk, dnWv,
                        pvWq, pvWk, pvWv, out);
    k_stats<<<dim3(7, 3), dim3(32, 32)>>>();
    k_mlp<<<dim3(NB / BT, 4), 256>>>(merged, a, tW1, tb1, tW2, tb2,
                                     eW1, eb1, eW2, eb2, eW3, eb3,
                                     gamma, beta, out);
}

// round 5
// speedup vs baseline: 1.2717x; 1.2717x over previous
#include <cuda_runtime.h>
#include <math.h>

#define NB   1024
#define NTOK 256
#define NV   200
#define BT   16

typedef unsigned long long u64;

// ---------------- device scratch ----------------
__device__ float g_M[245];            // Mu[7][14] | Md[7][14] | Mp[7][7]
__device__ float g_udp[3][NB][NV];
__device__ float g_mean[3][NV];
__device__ float g_rstd[3][NV];

// ---------------- helpers ----------------
__device__ __forceinline__ float warp_sum(float v) {
#pragma unroll
    for (int o = 16; o; o >>= 1) v += __shfl_xor_sync(0xffffffffu, v, o);
    return v;
}
__device__ __forceinline__ float warp_max(float v) {
#pragma unroll
    for (int o = 16; o; o >>= 1) v = fmaxf(v, __shfl_xor_sync(0xffffffffu, v, o));
    return v;
}
__device__ __forceinline__ u64 ffma2(u64 a, u64 b, u64 c) {
    u64 d;
    asm("fma.rn.f32x2 %0, %1, %2, %3;" : "=l"(d) : "l"(a), "l"(b), "l"(c));
    return d;
}
union F2U { float2 f; u64 u; };
__device__ __forceinline__ u64 pack2(float x, float y) {
    F2U t; t.f = make_float2(x, y); return t.u;
}
__device__ __forceinline__ float2 unpack2(u64 v) { F2U t; t.u = v; return t.f; }

// ---------------- kernel 0: M = Wq @ Wk^T (once) ----------------
__global__ void k_pre(const float* __restrict__ upWq, const float* __restrict__ upWk,
                      const float* __restrict__ dnWq, const float* __restrict__ dnWk,
                      const float* __restrict__ pvWq, const float* __restrict__ pvWk) {
    int t = threadIdx.x;
    if (t >= 245) return;
    const float *Wq, *Wk; int j, f;
    if (t < 98)       { Wq = upWq; Wk = upWk; j = t / 14;        f = t % 14; }
    else if (t < 196) { Wq = dnWq; Wk = dnWk; j = (t - 98) / 14; f = (t - 98) % 14; }
    else              { Wq = pvWq; Wk = pvWk; j = (t - 196) / 7; f = (t - 196) % 7; }
    const float4* q4 = (const float4*)(Wq + j * NV);
    const float4* k4 = (const float4*)(Wk + f * NV);
    float s = 0.f;
#pragma unroll 5
    for (int v = 0; v < NV / 4; v++) {
        float4 qa = q4[v], ka = k4[v];
        s += qa.x * ka.x + qa.y * ka.y + qa.z * ka.z + qa.w * ka.w;
    }
    g_M[t] = s;
}

// ---------------- kernel 1: attention, block-per-batch, coalesced ----------------
__global__ __launch_bounds__(256) void k_attn(
    const float* __restrict__ merged, const float* __restrict__ a,
    const float* __restrict__ upWv, const float* __restrict__ dnWv,
    const float* __restrict__ pvWv, float* __restrict__ out)
{
    __shared__ float feat[NTOK * 15];
    __shared__ float sM[245];        // Mu[7][14] | Md[7][14] | Mp[7][7]
    __shared__ float sqk[35];        // qku[14] | qkd[14] | qkp[7]
    __shared__ float wred[8][6];
    __shared__ float wpart[8][38];
    __shared__ float sred[38];       // Su,Sd,Sp | wfu[14] | wfd[14] | wfp[7]

    int b = blockIdx.x, t = threadIdx.x;
    int wid = t >> 5, lane = t & 31;

    // coalesced float4 staging of the 15KB batch row
    const float4* src4 = (const float4*)(merged + (size_t)b * NTOK * 15);
    float4* feat4 = (float4*)feat;
#pragma unroll
    for (int i = 0; i < 4; i++) {
        int idx = t + 256 * i;
        if (idx < 960) feat4[idx] = src4[idx];
    }
    if (b < 4) out[b * 256 + t] = 0.f;       // zero output once per replay
    if (t < 245) sM[t] = g_M[t];
    float a_b = a[b];
    __syncthreads();

    float subj_id = feat[0], subj_loc = feat[2];
    if (t < 35) {                             // qk = M^T @ ego
        float ego[7];
        ego[0] = 0.f; ego[1] = feat[1]; ego[2] = feat[2]; ego[3] = feat[3];
        ego[4] = feat[4]; ego[5] = feat[5]; ego[6] = a_b;
        float s = 0.f;
        if (t < 14) {
#pragma unroll
            for (int j = 0; j < 7; j++) s += ego[j] * sM[j * 14 + t];
        } else if (t < 28) {
            int f = t - 14;
#pragma unroll
            for (int j = 0; j < 7; j++) s += ego[j] * sM[98 + j * 14 + f];
        } else {
            int f = t - 28;
#pragma unroll
            for (int j = 0; j < 7; j++) s += ego[j] * sM[196 + j * 7 + f];
        }
        sqk[t] = s;
    }
    __syncthreads();

    // per-thread token
    float f[15];
#pragma unroll
    for (int q = 0; q < 15; q++) f[q] = feat[t * 15 + q];
    f[0] -= subj_id; f[7] -= subj_id;
    if (t == 0) f[6] = a_b;

    float s1 = 0.f, s2 = 0.f, s3 = 0.f;
#pragma unroll
    for (int q = 0; q < 14; q++) { s1 = fmaf(f[q], sqk[q], s1); s2 = fmaf(f[q], sqk[14 + q], s2); }
#pragma unroll
    for (int q = 0; q < 7; q++)  s3 = fmaf(f[q], sqk[28 + q], s3);

    const float scale = 0.07071067811865475f;   // 1/sqrt(200)
    bool fl1  = (f[14] == 1.0f);
    bool m_up = (f[2] < subj_loc) && fl1;
    bool m_dn = (f[2] > subj_loc) && fl1;
    bool m_pv = (f[14] == 0.0f);
    float su = m_up ? s1 * scale : -1e9f;
    float sd = m_dn ? s2 * scale : -1e9f;
    float sp = m_pv ? s3 * scale : -1e9f;

    // round A: max + count
    float mu = warp_max(su), md = warp_max(sd), mp = warp_max(sp);
    float cu = warp_sum(m_up ? 1.f : 0.f);
    float cd = warp_sum(m_dn ? 1.f : 0.f);
    float cp = warp_sum(m_pv ? 1.f : 0.f);
    if (lane == 0) {
        wred[wid][0] = mu; wred[wid][1] = md; wred[wid][2] = mp;
        wred[wid][3] = cu; wred[wid][4] = cd; wred[wid][5] = cp;
    }
    __syncthreads();
    float BU = wred[0][0], BD = wred[0][1], BP = wred[0][2];
    float CU = wred[0][3], CD = wred[0][4], CP = wred[0][5];
#pragma unroll
    for (int w = 1; w < 8; w++) {
        BU = fmaxf(BU, wred[w][0]); BD = fmaxf(BD, wred[w][1]); BP = fmaxf(BP, wred[w][2]);
        CU += wred[w][3]; CD += wred[w][4]; CP += wred[w][5];
    }
    float eu = __expf(su - BU), ed = __expf(sd - BD), ep = __expf(sp - BP);

    // round B: 38 joint sums (Su,Sd,Sp + 35 weighted feature sums)
    float vals[38];
    vals[0] = eu; vals[1] = ed; vals[2] = ep;
#pragma unroll
    for (int q = 0; q < 14; q++) { vals[3 + q] = eu * f[q]; vals[17 + q] = ed * f[q]; }
#pragma unroll
    for (int q = 0; q < 7; q++)  vals[31 + q] = ep * f[q];
#pragma unroll
    for (int i = 0; i < 38; i++) {
        float v = warp_sum(vals[i]);
        if (lane == 0) wpart[wid][i] = v;
    }
    __syncthreads();
    if (t < 38) {
        float s = 0.f;
#pragma unroll
        for (int w = 0; w < 8; w++) s += wpart[w][t];
        sred[t] = s;
    }
    __syncthreads();

    // out = (wf / S) @ Wv
    if (t < NV) {
        float iSu = (CU > 0.5f) ? 1.f / sred[0] : 0.f;
        float iSd = (CD > 0.5f) ? 1.f / sred[1] : 0.f;
        float iSp = (CP > 0.5f) ? 1.f / sred[2] : 0.f;
        float ou = 0.f, od = 0.f, op = 0.f;
#pragma unroll
        for (int q = 0; q < 14; q++) {
            ou = fmaf(sred[3 + q],  __ldg(&upWv[q * NV + t]), ou);
            od = fmaf(sred[17 + q], __ldg(&dnWv[q * NV + t]), od);
        }
#pragma unroll
        for (int q = 0; q < 7; q++)
            op = fmaf(sred[31 + q], __ldg(&pvWv[q * NV + t]), op);
        g_udp[0][b][t] = ou * iSu;
        g_udp[1][b][t] = od * iSd;
        g_udp[2][b][t] = op * iSp;
    }
}

// ---------------- kernel 2: batch-norm stats ----------------
__global__ void k_stats() {
    int k  = blockIdx.y;
    int v  = blockIdx.x * 32 + threadIdx.x;
    int ty = threadIdx.y;           // 0..31
    double s = 0.0, s2 = 0.0;
    if (v < NV) {
        for (int b = ty; b < NB; b += 32) {
            float x = g_udp[k][b][v];
            s  += (double)x;
            s2 += (double)x * (double)x;
        }
    }
    __shared__ double ss[32][33], ss2[32][33];
    ss[ty][threadIdx.x]  = s;
    ss2[ty][threadIdx.x] = s2;
    __syncthreads();
    if (ty == 0 && v < NV) {
        for (int y = 1; y < 32; y++) { s += ss[y][threadIdx.x]; s2 += ss2[y][threadIdx.x]; }
        double mean = s / (double)NB;
        double var  = s2 / (double)NB - mean * mean;
        g_mean[k][v] = (float)mean;
        g_rstd[k][v] = (float)(1.0 / sqrt(var + 1e-5));
    }
}

// ---------------- kernel 3: 200x200 GEMMs, f32x2, direct-LDG W ----------------
__global__ __launch_bounds__(256) void k_mlp(const float* __restrict__ merged,
                                             const float* __restrict__ a,
                                             const float* __restrict__ tW1,
                                             const float* __restrict__ tb1,
                                             const float* __restrict__ tW2,
                                             const float* __restrict__ tb2,
                                             const float* __restrict__ eW1,
                                             const float* __restrict__ eb1,
                                             const float* __restrict__ eW2,
                                             const float* __restrict__ eb2,
                                             const float* __restrict__ eW3,
                                             const float* __restrict__ eb3,
                                             const float* __restrict__ gamma,
                                             const float* __restrict__ beta,
                                             float* __restrict__ out) {
    int unit = blockIdx.y;        // 0..2 heads, 3 = ego net
    int b0   = blockIdx.x * BT;
    int t    = threadIdx.x;
    int ty   = t >> 6;            // 0..3 (warp-uniform)
    int tx   = t & 63;            // active < 50
    bool act = tx < 50;

    __shared__ float2 Xd[BT][NV];   // duplicated activations (25600 B)

    // ---- build X (duplicated) ----
    if (unit < 3) {
        for (int i = t; i < BT * NV; i += 256) {
            int bb = i / NV, v = i - bb * NV;
            float x = g_udp[unit][b0 + bb][v];
            x = gamma[v] * (x - g_mean[unit][v]) * g_rstd[unit][v] + beta[v];
            Xd[bb][v] = make_float2(x, x);
        }
    } else if (t < NV) {
        float w0 = eW1[t], w1 = eW1[NV + t], w2 = eW1[2 * NV + t], w3 = eW1[3 * NV + t];
        float bb1 = eb1[t];
        for (int bb = 0; bb < BT; bb++) {
            const float* mr = merged + (size_t)(b0 + bb) * NTOK * 15;
            float h = fmaxf(mr[3] * w0 + mr[4] * w1 + mr[5] * w2 + a[b0 + bb] * w3 + bb1, 0.f);
            Xd[bb][t] = make_float2(h, h);
        }
    }
    __syncthreads();

    const float* Wg   = (unit < 3) ? tW1 + (size_t)unit * NV * NV : eW2;
    const float* bias = (unit < 3) ? tb1 + unit * NV : eb2;

    int o0 = tx * 4;
    u64 acc[4][2];
    if (act) {
        acc[0][0] = pack2(bias[o0], bias[o0 + 1]);
        acc[0][1] = pack2(bias[o0 + 2], bias[o0 + 3]);
#pragma unroll
        for (int i = 1; i < 4; i++) { acc[i][0] = acc[0][0]; acc[i][1] = acc[0][1]; }

#pragma unroll 4
        for (int k = 0; k < NV; k += 2) {
            ulonglong2 w0 = __ldg((const ulonglong2*)(Wg + (size_t)k * NV + o0));
            ulonglong2 w1 = __ldg((const ulonglong2*)(Wg + (size_t)(k + 1) * NV + o0));
#pragma unroll
            for (int i = 0; i < 4; i++) {
                ulonglong2 x = *reinterpret_cast<const ulonglong2*>(&Xd[ty * 4 + i][k]);
                acc[i][0] = ffma2(x.x, w0.x, acc[i][0]);
                acc[i][1] = ffma2(x.x, w0.y, acc[i][1]);
                acc[i][0] = ffma2(x.y, w1.x, acc[i][0]);
                acc[i][1] = ffma2(x.y, w1.y, acc[i][1]);
            }
        }
    }

    // ---- epilogue: activation, *W2, reduce ----
    float p[4] = {0.f, 0.f, 0.f, 0.f};
    if (act) {
        float w2v[4];
#pragma unroll
        for (int j = 0; j < 4; j++)
            w2v[j] = (unit < 3) ? tW2[unit * NV + o0 + j] : eW3[o0 + j];
#pragma unroll
        for (int i = 0; i < 4; i++) {
            float2 v01 = unpack2(acc[i][0]);
            float2 v23 = unpack2(acc[i][1]);
            float v[4] = {v01.x, v01.y, v23.x, v23.y};
            float s = 0.f;
#pragma unroll
            for (int j = 0; j < 4; j++) {
                float x = v[j];
                x = (unit < 3) ? (x > 0.f ? x : expm1f(x)) : fmaxf(x, 0.f);
                s = fmaf(x, w2v[j], s);
            }
            p[i] = s;
        }
    }
    __syncthreads();                       // done reading Xd
    float* red = (float*)&Xd[0][0];        // red[50][17]
    if (act) {
#pragma unroll
        for (int i = 0; i < 4; i++) red[tx * 17 + ty * 4 + i] = p[i];
    }
    __syncthreads();
    if (t < BT) {
        float s = 0.f;
        for (int j = 0; j < 50; j++) s += red[j * 17 + t];
        float fb = (unit < 3) ? tb2[unit] : eb3[0];
        atomicAdd(&out[b0 + t], s + fb);
    }
}

// ---------------- launch ----------------
extern "C" void kernel_launch(void* const* d_in, const int* in_sizes, int n_in,
                              void* d_out, int out_size) {
    (void)in_sizes; (void)n_in; (void)out_size;
    const float* merged = (const float*)d_in[0];
    const float* a      = (const float*)d_in[1];
    const float* upWq   = (const float*)d_in[2];
    const float* upWk   = (const float*)d_in[3];
    const float* upWv   = (const float*)d_in[4];
    const float* dnWq   = (const float*)d_in[5];
    const float* dnWk   = (const float*)d_in[6];
    const float* dnWv   = (const float*)d_in[7];
    const float* pvWq   = (const float*)d_in[8];
    const float* pvWk   = (const float*)d_in[9];
    const float* pvWv   = (const float*)d_in[10];
    const float* tW1    = (const float*)d_in[11];
    const float* tb1    = (const float*)d_in[12];
    const float* tW2    = (const float*)d_in[13];
    const float* tb2    = (const float*)d_in[14];
    const float* eW1    = (const float*)d_in[15];
    const float* eb1    = (const float*)d_in[16];
    const float* eW2    = (const float*)d_in[17];
    const float* eb2    = (const float*)d_in[18];
    const float* eW3    = (const float*)d_in[19];
    const float* eb3    = (const float*)d_in[20];
    const float* gamma  = (const float*)d_in[21];
    const float* beta   = (const float*)d_in[22];
    float* out = (float*)d_out;

    k_pre<<<1, 256>>>(upWq, upWk, dnWq, dnWk, pvWq, pvWk);
    k_attn<<<NB, 256>>>(merged, a, upWv, dnWv, pvWv, out);
    k_stats<<<dim3(7, 3), dim3(32, 32)>>>();
    k_mlp<<<dim3(NB / BT, 4), 256>>>(merged, a, tW1, tb1, tW2, tb2,
                                     eW1, eb1, eW2, eb2, eW3, eb3,
                                     gamma, beta, out);
}

// round 6
// speedup vs baseline: 1.9252x; 1.5139x over previous
#include <cuda_runtime.h>
#include <math.h>

#define NB   1024
#define NTOK 256
#define NV   200
#define BT   16
#define KC   10
#define NCH  (NV / KC)   // 20 chunks

typedef unsigned long long u64;

// ---------------- device scratch ----------------
__device__ float g_M[245];            // Mu[7][14] | Md[7][14] | Mp[7][7]
__device__ float g_udp[3][NB][NV];
__device__ float g_mean[3][NV];
__device__ float g_rstd[3][NV];

// ---------------- helpers ----------------
__device__ __forceinline__ float warp_sum(float v) {
#pragma unroll
    for (int o = 16; o; o >>= 1) v += __shfl_xor_sync(0xffffffffu, v, o);
    return v;
}
__device__ __forceinline__ float warp_max(float v) {
#pragma unroll
    for (int o = 16; o; o >>= 1) v = fmaxf(v, __shfl_xor_sync(0xffffffffu, v, o));
    return v;
}
__device__ __forceinline__ u64 ffma2(u64 a, u64 b, u64 c) {
    u64 d;
    asm("fma.rn.f32x2 %0, %1, %2, %3;" : "=l"(d) : "l"(a), "l"(b), "l"(c));
    return d;
}
union F2U { float2 f; u64 u; };
__device__ __forceinline__ u64 pack2(float x, float y) {
    F2U t; t.f = make_float2(x, y); return t.u;
}
__device__ __forceinline__ float2 unpack2(u64 v) { F2U t; t.u = v; return t.f; }
__device__ __forceinline__ void cp16(unsigned dst, const void* src) {
    asm volatile("cp.async.cg.shared.global [%0], [%1], 16;" :: "r"(dst), "l"(src));
}
__device__ __forceinline__ void cp_commit() {
    asm volatile("cp.async.commit_group;");
}
template <int N>
__device__ __forceinline__ void cp_wait() {
    asm volatile("cp.async.wait_group %0;" :: "n"(N));
}

// ---------------- kernel 0: M = Wq @ Wk^T (once) ----------------
__global__ void k_pre(const float* __restrict__ upWq, const float* __restrict__ upWk,
                      const float* __restrict__ dnWq, const float* __restrict__ dnWk,
                      const float* __restrict__ pvWq, const float* __restrict__ pvWk) {
    int t = threadIdx.x;
    if (t >= 245) return;
    const float *Wq, *Wk; int j, f;
    if (t < 98)       { Wq = upWq; Wk = upWk; j = t / 14;        f = t % 14; }
    else if (t < 196) { Wq = dnWq; Wk = dnWk; j = (t - 98) / 14; f = (t - 98) % 14; }
    else              { Wq = pvWq; Wk = pvWk; j = (t - 196) / 7; f = (t - 196) % 7; }
    const float4* q4 = (const float4*)(Wq + j * NV);
    const float4* k4 = (const float4*)(Wk + f * NV);
    float s = 0.f;
#pragma unroll 5
    for (int v = 0; v < NV / 4; v++) {
        float4 qa = q4[v], ka = k4[v];
        s += qa.x * ka.x + qa.y * ka.y + qa.z * ka.z + qa.w * ka.w;
    }
    g_M[t] = s;
}

// ---------------- kernel 1: attention, block-per-batch ----------------
__global__ __launch_bounds__(256) void k_attn(
    const float* __restrict__ merged, const float* __restrict__ a,
    const float* __restrict__ upWv, const float* __restrict__ dnWv,
    const float* __restrict__ pvWv, float* __restrict__ out)
{
    __shared__ float feat[NTOK * 15];
    __shared__ float sM[245];
    __shared__ float sqk[35];
    __shared__ float wred[8][6];
    __shared__ float wpart[8][38];
    __shared__ float sred[38];

    int b = blockIdx.x, t = threadIdx.x;
    int wid = t >> 5, lane = t & 31;

    const float4* src4 = (const float4*)(merged + (size_t)b * NTOK * 15);
    float4* feat4 = (float4*)feat;
#pragma unroll
    for (int i = 0; i < 4; i++) {
        int idx = t + 256 * i;
        if (idx < 960) feat4[idx] = src4[idx];
    }
    if (b < 4) out[b * 256 + t] = 0.f;
    if (t < 245) sM[t] = g_M[t];
    float a_b = a[b];
    __syncthreads();

    float subj_id = feat[0], subj_loc = feat[2];
    if (t < 35) {
        float ego[7];
        ego[0] = 0.f; ego[1] = feat[1]; ego[2] = feat[2]; ego[3] = feat[3];
        ego[4] = feat[4]; ego[5] = feat[5]; ego[6] = a_b;
        float s = 0.f;
        if (t < 14) {
#pragma unroll
            for (int j = 0; j < 7; j++) s += ego[j] * sM[j * 14 + t];
        } else if (t < 28) {
            int f = t - 14;
#pragma unroll
            for (int j = 0; j < 7; j++) s += ego[j] * sM[98 + j * 14 + f];
        } else {
            int f = t - 28;
#pragma unroll
            for (int j = 0; j < 7; j++) s += ego[j] * sM[196 + j * 7 + f];
        }
        sqk[t] = s;
    }
    __syncthreads();

    float f[15];
#pragma unroll
    for (int q = 0; q < 15; q++) f[q] = feat[t * 15 + q];
    f[0] -= subj_id; f[7] -= subj_id;
    if (t == 0) f[6] = a_b;

    float s1 = 0.f, s2 = 0.f, s3 = 0.f;
#pragma unroll
    for (int q = 0; q < 14; q++) { s1 = fmaf(f[q], sqk[q], s1); s2 = fmaf(f[q], sqk[14 + q], s2); }
#pragma unroll
    for (int q = 0; q < 7; q++)  s3 = fmaf(f[q], sqk[28 + q], s3);

    const float scale = 0.07071067811865475f;
    bool fl1  = (f[14] == 1.0f);
    bool m_up = (f[2] < subj_loc) && fl1;
    bool m_dn = (f[2] > subj_loc) && fl1;
    bool m_pv = (f[14] == 0.0f);
    float su = m_up ? s1 * scale : -1e9f;
    float sd = m_dn ? s2 * scale : -1e9f;
    float sp = m_pv ? s3 * scale : -1e9f;

    float mu = warp_max(su), md = warp_max(sd), mp = warp_max(sp);
    float cu = warp_sum(m_up ? 1.f : 0.f);
    float cd = warp_sum(m_dn ? 1.f : 0.f);
    float cp = warp_sum(m_pv ? 1.f : 0.f);
    if (lane == 0) {
        wred[wid][0] = mu; wred[wid][1] = md; wred[wid][2] = mp;
        wred[wid][3] = cu; wred[wid][4] = cd; wred[wid][5] = cp;
    }
    __syncthreads();
    float BU = wred[0][0], BD = wred[0][1], BP = wred[0][2];
    float CU = wred[0][3], CD = wred[0][4], CP = wred[0][5];
#pragma unroll
    for (int w = 1; w < 8; w++) {
        BU = fmaxf(BU, wred[w][0]); BD = fmaxf(BD, wred[w][1]); BP = fmaxf(BP, wred[w][2]);
        CU += wred[w][3]; CD += wred[w][4]; CP += wred[w][5];
    }
    float eu = __expf(su - BU), ed = __expf(sd - BD), ep = __expf(sp - BP);

    float vals[38];
    vals[0] = eu; vals[1] = ed; vals[2] = ep;
#pragma unroll
    for (int q = 0; q < 14; q++) { vals[3 + q] = eu * f[q]; vals[17 + q] = ed * f[q]; }
#pragma unroll
    for (int q = 0; q < 7; q++)  vals[31 + q] = ep * f[q];
#pragma unroll
    for (int i = 0; i < 38; i++) {
        float v = warp_sum(vals[i]);
        if (lane == 0) wpart[wid][i] = v;
    }
    __syncthreads();
    if (t < 38) {
        float s = 0.f;
#pragma unroll
        for (int w = 0; w < 8; w++) s += wpart[w][t];
        sred[t] = s;
    }
    __syncthreads();

    if (t < NV) {
        float iSu = (CU > 0.5f) ? 1.f / sred[0] : 0.f;
        float iSd = (CD > 0.5f) ? 1.f / sred[1] : 0.f;
        float iSp = (CP > 0.5f) ? 1.f / sred[2] : 0.f;
        float ou = 0.f, od = 0.f, op = 0.f;
#pragma unroll
        for (int q = 0; q < 14; q++) {
            ou = fmaf(sred[3 + q],  __ldg(&upWv[q * NV + t]), ou);
            od = fmaf(sred[17 + q], __ldg(&dnWv[q * NV + t]), od);
        }
#pragma unroll
        for (int q = 0; q < 7; q++)
            op = fmaf(sred[31 + q], __ldg(&pvWv[q * NV + t]), op);
        g_udp[0][b][t] = ou * iSu;
        g_udp[1][b][t] = od * iSd;
        g_udp[2][b][t] = op * iSp;
    }
}

// ---------------- kernel 2: batch-norm stats (fp32, tree reduce) ----------------
__global__ void k_stats() {
    int k  = blockIdx.y;
    int vx = threadIdx.x;
    int by = threadIdx.y;           // 0..31
    int v  = blockIdx.x * 32 + vx;
    float s = 0.f, s2 = 0.f;
    if (v < NV) {
#pragma unroll 4
        for (int j = 0; j < 32; j++) {
            float x = g_udp[k][by + 32 * j][v];
            s += x;
            s2 = fmaf(x, x, s2);
        }
    }
    __shared__ float ss[32][33], ss2[32][33];
    ss[by][vx]  = s;
    ss2[by][vx] = s2;
    __syncthreads();
#pragma unroll
    for (int off = 16; off; off >>= 1) {
        if (by < off) {
            ss[by][vx]  += ss[by + off][vx];
            ss2[by][vx] += ss2[by + off][vx];
        }
        __syncthreads();
    }
    if (by == 0 && v < NV) {
        float mean = ss[0][vx] * (1.f / NB);
        float var  = ss2[0][vx] * (1.f / NB) - mean * mean;
        g_mean[k][v] = mean;
        g_rstd[k][v] = rsqrtf(var + 1e-5f);
    }
}

// ---------------- kernel 3: 200x200 GEMMs, f32x2 + cp.async double buffer ----------------
// 256 threads, BT=16 batches, 200 outputs. ty=t>>6 (4 batches each), tx=t&63 (<50 active, 4 outs).
__global__ __launch_bounds__(256) void k_mlp(const float* __restrict__ merged,
                                             const float* __restrict__ a,
                                             const float* __restrict__ tW1,
                                             const float* __restrict__ tb1,
                                             const float* __restrict__ tW2,
                                             const float* __restrict__ tb2,
                                             const float* __restrict__ eW1,
                                             const float* __restrict__ eb1,
                                             const float* __restrict__ eW2,
                                             const float* __restrict__ eb2,
                                             const float* __restrict__ eW3,
                                             const float* __restrict__ eb3,
                                             const float* __restrict__ gamma,
                                             const float* __restrict__ beta,
                                             float* __restrict__ out) {
    int unit = blockIdx.y;        // 0..2 heads, 3 = ego net
    int b0   = blockIdx.x * BT;
    int t    = threadIdx.x;
    int ty   = t >> 6;            // 0..3 (warp-uniform)
    int tx   = t & 63;            // active < 50
    bool act = tx < 50;

    __shared__ float2 Xd[BT][NV];          // 25600 B, duplicated activations
    __shared__ float  Wbuf[2][KC][NV];     // 2 x 8000 B

    // ---- build X (duplicated) ----
    if (unit < 3) {
        for (int i = t; i < BT * NV; i += 256) {
            int bb = i / NV, v = i - bb * NV;
            float x = g_udp[unit][b0 + bb][v];
            x = gamma[v] * (x - g_mean[unit][v]) * g_rstd[unit][v] + beta[v];
            Xd[bb][v] = make_float2(x, x);
        }
    } else if (t < NV) {
        float w0 = eW1[t], w1 = eW1[NV + t], w2 = eW1[2 * NV + t], w3 = eW1[3 * NV + t];
        float bb1 = eb1[t];
        for (int bb = 0; bb < BT; bb++) {
            const float* mr = merged + (size_t)(b0 + bb) * NTOK * 15;
            float h = fmaxf(mr[3] * w0 + mr[4] * w1 + mr[5] * w2 + a[b0 + bb] * w3 + bb1, 0.f);
            Xd[bb][t] = make_float2(h, h);
        }
    }

    const float* Wg   = (unit < 3) ? tW1 + (size_t)unit * NV * NV : eW2;
    const float* bias = (unit < 3) ? tb1 + unit * NV : eb2;

    // stage chunk 0
    {
        unsigned sb = (unsigned)__cvta_generic_to_shared(&Wbuf[0][0][0]);
        for (int i = t; i < KC * NV / 4; i += 256)
            cp16(sb + i * 16, Wg + i * 4);
        cp_commit();
    }

    int o0 = tx * 4;
    u64 acc[4][2];
    acc[0][0] = act ? pack2(bias[o0], bias[o0 + 1]) : 0ull;
    acc[0][1] = act ? pack2(bias[o0 + 2], bias[o0 + 3]) : 0ull;
#pragma unroll
    for (int i = 1; i < 4; i++) { acc[i][0] = acc[0][0]; acc[i][1] = acc[0][1]; }

    for (int c = 0; c < NCH; c++) {
        if (c + 1 < NCH) {
            unsigned sb = (unsigned)__cvta_generic_to_shared(&Wbuf[(c + 1) & 1][0][0]);
            const float* gsrc = Wg + (size_t)(c + 1) * KC * NV;
            for (int i = t; i < KC * NV / 4; i += 256)
                cp16(sb + i * 16, gsrc + i * 4);
            cp_commit();
            cp_wait<1>();
        } else {
            cp_wait<0>();
        }
        __syncthreads();
        if (act) {
            const float* Wb = &Wbuf[c & 1][0][0];
            int k0 = c * KC;
#pragma unroll
            for (int kc = 0; kc < KC; kc += 2) {
                ulonglong2 w0 = *(const ulonglong2*)(Wb + kc * NV + o0);
                ulonglong2 w1 = *(const ulonglong2*)(Wb + (kc + 1) * NV + o0);
#pragma unroll
                for (int i = 0; i < 4; i++) {
                    ulonglong2 x = *(const ulonglong2*)&Xd[ty * 4 + i][k0 + kc];
                    acc[i][0] = ffma2(x.x, w0.x, acc[i][0]);
                    acc[i][1] = ffma2(x.x, w0.y, acc[i][1]);
                    acc[i][0] = ffma2(x.y, w1.x, acc[i][0]);
                    acc[i][1] = ffma2(x.y, w1.y, acc[i][1]);
                }
            }
        }
        __syncthreads();   // protect Wbuf[c&1] before restage at c+2
    }

    // ---- epilogue: activation, *W2, reduce ----
    float p[4] = {0.f, 0.f, 0.f, 0.f};
    if (act) {
        float w2v[4];
#pragma unroll
        for (int j = 0; j < 4; j++)
            w2v[j] = (unit < 3) ? tW2[unit * NV + o0 + j] : eW3[o0 + j];
#pragma unroll
        for (int i = 0; i < 4; i++) {
            float2 v01 = unpack2(acc[i][0]);
            float2 v23 = unpack2(acc[i][1]);
            float v[4] = {v01.x, v01.y, v23.x, v23.y};
            float s = 0.f;
#pragma unroll
            for (int j = 0; j < 4; j++) {
                float x = v[j];
                x = (unit < 3) ? (x > 0.f ? x : expm1f(x)) : fmaxf(x, 0.f);
                s = fmaf(x, w2v[j], s);
            }
            p[i] = s;
        }
    }
    __syncthreads();                       // done reading Xd
    float* red = (float*)&Xd[0][0];        // red[50][17]
    if (act) {
#pragma unroll
        for (int i = 0; i < 4; i++) red[tx * 17 + ty * 4 + i] = p[i];
    }
    __syncthreads();
    if (t < BT) {
        float s = 0.f;
        for (int j = 0; j < 50; j++) s += red[j * 17 + t];
        float fb = (unit < 3) ? tb2[unit] : eb3[0];
        atomicAdd(&out[b0 + t], s + fb);
    }
}

// ---------------- launch ----------------
extern "C" void kernel_launch(void* const* d_in, const int* in_sizes, int n_in,
                              void* d_out, int out_size) {
    (void)in_sizes; (void)n_in; (void)out_size;
    const float* merged = (const float*)d_in[0];
    const float* a      = (const float*)d_in[1];
    const float* upWq   = (const float*)d_in[2];
    const float* upWk   = (const float*)d_in[3];
    const float* upWv   = (const float*)d_in[4];
    const float* dnWq   = (const float*)d_in[5];
    const float* dnWk   = (const float*)d_in[6];
    const float* dnWv   = (const float*)d_in[7];
    const float* pvWq   = (const float*)d_in[8];
    const float* pvWk   = (const float*)d_in[9];
    const float* pvWv   = (const float*)d_in[10];
    const float* tW1    = (const float*)d_in[11];
    const float* tb1    = (const float*)d_in[12];
    const float* tW2    = (const float*)d_in[13];
    const float* tb2    = (const float*)d_in[14];
    const float* eW1    = (const float*)d_in[15];
    const float* eb1    = (const float*)d_in[16];
    const float* eW2    = (const float*)d_in[17];
    const float* eb2    = (const float*)d_in[18];
    const float* eW3    = (const float*)d_in[19];
    const float* eb3    = (const float*)d_in[20];
    const float* gamma  = (const float*)d_in[21];
    const float* beta   = (const float*)d_in[22];
    float* out = (float*)d_out;

    k_pre<<<1, 256>>>(upWq, upWk, dnWq, dnWk, pvWq, pvWk);
    k_attn<<<NB, 256>>>(merged, a, upWv, dnWv, pvWv, out);
    k_stats<<<dim3(7, 3), dim3(32, 32)>>>();
    k_mlp<<<dim3(NB / BT, 4), 256>>>(merged, a, tW1, tb1, tW2, tb2,
                                     eW1, eb1, eW2, eb2, eW3, eb3,
                                     gamma, beta, out);
}

// round 7
// speedup vs baseline: 2.0823x; 1.0816x over previous
#include <cuda_runtime.h>
#include <math.h>

#define NB   1024
#define NTOK 256
#define NV   200
#define BT   32
#define KC   10
#define NCH  (NV / KC)   // 20 chunks

typedef unsigned long long u64;

// ---------------- device scratch ----------------
__device__ float g_udp[3][NB][NV];
__device__ float g_mean[3][NV];
__device__ float g_rstd[3][NV];

// ---------------- helpers ----------------
__device__ __forceinline__ float warp_sum(float v) {
#pragma unroll
    for (int o = 16; o; o >>= 1) v += __shfl_xor_sync(0xffffffffu, v, o);
    return v;
}
__device__ __forceinline__ float warp_max(float v) {
#pragma unroll
    for (int o = 16; o; o >>= 1) v = fmaxf(v, __shfl_xor_sync(0xffffffffu, v, o));
    return v;
}
__device__ __forceinline__ u64 ffma2(u64 a, u64 b, u64 c) {
    u64 d;
    asm("fma.rn.f32x2 %0, %1, %2, %3;" : "=l"(d) : "l"(a), "l"(b), "l"(c));
    return d;
}
union F2U { float2 f; u64 u; };
__device__ __forceinline__ u64 pack2(float x, float y) {
    F2U t; t.f = make_float2(x, y); return t.u;
}
__device__ __forceinline__ float2 unpack2(u64 v) { F2U t; t.u = v; return t.f; }
__device__ __forceinline__ void cp16(unsigned dst, const void* src) {
    asm volatile("cp.async.cg.shared.global [%0], [%1], 16;" :: "r"(dst), "l"(src));
}
__device__ __forceinline__ void cp_commit() {
    asm volatile("cp.async.commit_group;");
}
template <int N>
__device__ __forceinline__ void cp_wait() {
    asm volatile("cp.async.wait_group %0;" :: "n"(N));
}

// ---------------- kernel 1: attention, block-per-batch (pre fused) ----------------
__global__ __launch_bounds__(256) void k_attn(
    const float* __restrict__ merged, const float* __restrict__ a,
    const float* __restrict__ upWq, const float* __restrict__ upWk, const float* __restrict__ upWv,
    const float* __restrict__ dnWq, const float* __restrict__ dnWk, const float* __restrict__ dnWv,
    const float* __restrict__ pvWq, const float* __restrict__ pvWk, const float* __restrict__ pvWv,
    float* __restrict__ out)
{
    __shared__ float feat[NTOK * 15];
    __shared__ float sq[3][NV];      // q_u, q_d, q_p
    __shared__ float sqk[35];        // qku[14] | qkd[14] | qkp[7]
    __shared__ float wred[8][6];
    __shared__ float wpart[8][38];
    __shared__ float sred[38];

    int b = blockIdx.x, t = threadIdx.x;
    int wid = t >> 5, lane = t & 31;

    const float4* src4 = (const float4*)(merged + (size_t)b * NTOK * 15);
    float4* feat4 = (float4*)feat;
#pragma unroll
    for (int i = 0; i < 4; i++) {
        int idx = t + 256 * i;
        if (idx < 960) feat4[idx] = src4[idx];
    }
    if (b < 4) out[b * 256 + t] = 0.f;
    float a_b = a[b];
    __syncthreads();

    float subj_id = feat[0], subj_loc = feat[2];

    // q = Wq^T @ ego  (ego = [0, f1..f5, a_b]; j=0 term is zero)
    if (t < NV) {
        float e1 = feat[1], e2 = feat[2], e3 = feat[3], e4 = feat[4], e5 = feat[5];
        float qu, qd, qp;
        qu = e1 * __ldg(upWq + NV + t) + e2 * __ldg(upWq + 2 * NV + t)
           + e3 * __ldg(upWq + 3 * NV + t) + e4 * __ldg(upWq + 4 * NV + t)
           + e5 * __ldg(upWq + 5 * NV + t) + a_b * __ldg(upWq + 6 * NV + t);
        qd = e1 * __ldg(dnWq + NV + t) + e2 * __ldg(dnWq + 2 * NV + t)
           + e3 * __ldg(dnWq + 3 * NV + t) + e4 * __ldg(dnWq + 4 * NV + t)
           + e5 * __ldg(dnWq + 5 * NV + t) + a_b * __ldg(dnWq + 6 * NV + t);
        qp = e1 * __ldg(pvWq + NV + t) + e2 * __ldg(pvWq + 2 * NV + t)
           + e3 * __ldg(pvWq + 3 * NV + t) + e4 * __ldg(pvWq + 4 * NV + t)
           + e5 * __ldg(pvWq + 5 * NV + t) + a_b * __ldg(pvWq + 6 * NV + t);
        sq[0][t] = qu; sq[1][t] = qd; sq[2][t] = qp;
    }
    __syncthreads();

    // qk[f] = q . Wk[f]  — 35 warp-level dots, warp w handles f = w + 8m
#pragma unroll
    for (int m = 0; m < 5; m++) {
        int f = wid + 8 * m;
        if (f < 35) {
            const float* Wk;
            const float* qv;
            int fr;
            if (f < 14)      { Wk = upWk; qv = sq[0]; fr = f; }
            else if (f < 28) { Wk = dnWk; qv = sq[1]; fr = f - 14; }
            else             { Wk = pvWk; qv = sq[2]; fr = f - 28; }
            float s = 0.f;
#pragma unroll
            for (int k = 0; k < 7; k++) {
                int v = lane + 32 * k;
                if (v < NV) s = fmaf(qv[v], __ldg(Wk + fr * NV + v), s);
            }
            s = warp_sum(s);
            if (lane == 0) sqk[f] = s;
        }
    }
    __syncthreads();

    // per-thread token
    float f[15];
#pragma unroll
    for (int q = 0; q < 15; q++) f[q] = feat[t * 15 + q];
    f[0] -= subj_id; f[7] -= subj_id;
    if (t == 0) f[6] = a_b;

    float s1 = 0.f, s2 = 0.f, s3 = 0.f;
#pragma unroll
    for (int q = 0; q < 14; q++) { s1 = fmaf(f[q], sqk[q], s1); s2 = fmaf(f[q], sqk[14 + q], s2); }
#pragma unroll
    for (int q = 0; q < 7; q++)  s3 = fmaf(f[q], sqk[28 + q], s3);

    const float scale = 0.07071067811865475f;
    bool fl1  = (f[14] == 1.0f);
    bool m_up = (f[2] < subj_loc) && fl1;
    bool m_dn = (f[2] > subj_loc) && fl1;
    bool m_pv = (f[14] == 0.0f);
    float su = m_up ? s1 * scale : -1e9f;
    float sd = m_dn ? s2 * scale : -1e9f;
    float sp = m_pv ? s3 * scale : -1e9f;

    float mu = warp_max(su), md = warp_max(sd), mp = warp_max(sp);
    float cu = warp_sum(m_up ? 1.f : 0.f);
    float cd = warp_sum(m_dn ? 1.f : 0.f);
    float cp = warp_sum(m_pv ? 1.f : 0.f);
    if (lane == 0) {
        wred[wid][0] = mu; wred[wid][1] = md; wred[wid][2] = mp;
        wred[wid][3] = cu; wred[wid][4] = cd; wred[wid][5] = cp;
    }
    __syncthreads();
    float BU = wred[0][0], BD = wred[0][1], BP = wred[0][2];
    float CU = wred[0][3], CD = wred[0][4], CP = wred[0][5];
#pragma unroll
    for (int w = 1; w < 8; w++) {
        BU = fmaxf(BU, wred[w][0]); BD = fmaxf(BD, wred[w][1]); BP = fmaxf(BP, wred[w][2]);
        CU += wred[w][3]; CD += wred[w][4]; CP += wred[w][5];
    }
    float eu = __expf(su - BU), ed = __expf(sd - BD), ep = __expf(sp - BP);

    float vals[38];
    vals[0] = eu; vals[1] = ed; vals[2] = ep;
#pragma unroll
    for (int q = 0; q < 14; q++) { vals[3 + q] = eu * f[q]; vals[17 + q] = ed * f[q]; }
#pragma unroll
    for (int q = 0; q < 7; q++)  vals[31 + q] = ep * f[q];
#pragma unroll
    for (int i = 0; i < 38; i++) {
        float v = warp_sum(vals[i]);
        if (lane == 0) wpart[wid][i] = v;
    }
    __syncthreads();
    if (t < 38) {
        float s = 0.f;
#pragma unroll
        for (int w = 0; w < 8; w++) s += wpart[w][t];
        sred[t] = s;
    }
    __syncthreads();

    if (t < NV) {
        float iSu = (CU > 0.5f) ? 1.f / sred[0] : 0.f;
        float iSd = (CD > 0.5f) ? 1.f / sred[1] : 0.f;
        float iSp = (CP > 0.5f) ? 1.f / sred[2] : 0.f;
        float ou = 0.f, od = 0.f, op = 0.f;
#pragma unroll
        for (int q = 0; q < 14; q++) {
            ou = fmaf(sred[3 + q],  __ldg(&upWv[q * NV + t]), ou);
            od = fmaf(sred[17 + q], __ldg(&dnWv[q * NV + t]), od);
        }
#pragma unroll
        for (int q = 0; q < 7; q++)
            op = fmaf(sred[31 + q], __ldg(&pvWv[q * NV + t]), op);
        g_udp[0][b][t] = ou * iSu;
        g_udp[1][b][t] = od * iSd;
        g_udp[2][b][t] = op * iSp;
    }
}

// ---------------- kernel 2: batch-norm stats (fp32, tree reduce) ----------------
__global__ void k_stats() {
    int k  = blockIdx.y;
    int vx = threadIdx.x;
    int by = threadIdx.y;
    int v  = blockIdx.x * 32 + vx;
    float s = 0.f, s2 = 0.f;
    if (v < NV) {
#pragma unroll 4
        for (int j = 0; j < 32; j++) {
            float x = g_udp[k][by + 32 * j][v];
            s += x;
            s2 = fmaf(x, x, s2);
        }
    }
    __shared__ float ss[32][33], ss2[32][33];
    ss[by][vx]  = s;
    ss2[by][vx] = s2;
    __syncthreads();
#pragma unroll
    for (int off = 16; off; off >>= 1) {
        if (by < off) {
            ss[by][vx]  += ss[by + off][vx];
            ss2[by][vx] += ss2[by + off][vx];
        }
        __syncthreads();
    }
    if (by == 0 && v < NV) {
        float mean = ss[0][vx] * (1.f / NB);
        float var  = ss2[0][vx] * (1.f / NB) - mean * mean;
        g_mean[k][v] = mean;
        g_rstd[k][v] = rsqrtf(var + 1e-5f);
    }
}

// ---------------- kernel 3: 200x200 GEMMs, BT=32, 8x4 micro-tile ----------------
// 256 threads. ty=t>>6 (0..3): 8 batches each. tx=t&63 (<50 active): 4 outputs.
// Per 2k per warp: 2 LDS.128 (W) + 8 LDS.128 bcast (X) + 32 FFMA2.
__global__ __launch_bounds__(256) void k_mlp(const float* __restrict__ merged,
                                             const float* __restrict__ a,
                                             const float* __restrict__ tW1,
                                             const float* __restrict__ tb1,
                                             const float* __restrict__ tW2,
                                             const float* __restrict__ tb2,
                                             const float* __restrict__ eW1,
                                             const float* __restrict__ eb1,
                                             const float* __restrict__ eW2,
                                             const float* __restrict__ eb2,
                                             const float* __restrict__ eW3,
                                             const float* __restrict__ eb3,
                                             const float* __restrict__ gamma,
                                             const float* __restrict__ beta,
                                             float* __restrict__ out) {
    int unit = blockIdx.y;        // 0..2 heads, 3 = ego net
    int b0   = blockIdx.x * BT;
    int t    = threadIdx.x;
    int ty   = t >> 6;            // 0..3 (warp-uniform)
    int tx   = t & 63;            // active < 50
    bool act = tx < 50;

    __shared__ float2 Xd[BT][NV];          // 51200 B, duplicated activations
    __shared__ float  Wbuf[2][KC][NV];     // 2 x 8000 B

    // ---- build X (duplicated) ----
    if (unit < 3) {
        for (int i = t; i < BT * NV; i += 256) {
            int bb = i / NV, v = i - bb * NV;
            float x = g_udp[unit][b0 + bb][v];
            x = gamma[v] * (x - g_mean[unit][v]) * g_rstd[unit][v] + beta[v];
            Xd[bb][v] = make_float2(x, x);
        }
    } else if (t < NV) {
        float w0 = eW1[t], w1 = eW1[NV + t], w2 = eW1[2 * NV + t], w3 = eW1[3 * NV + t];
        float bb1 = eb1[t];
        for (int bb = 0; bb < BT; bb++) {
            const float* mr = merged + (size_t)(b0 + bb) * NTOK * 15;
            float h = fmaxf(mr[3] * w0 + mr[4] * w1 + mr[5] * w2 + a[b0 + bb] * w3 + bb1, 0.f);
            Xd[bb][t] = make_float2(h, h);
        }
    }

    const float* Wg   = (unit < 3) ? tW1 + (size_t)unit * NV * NV : eW2;
    const float* bias = (unit < 3) ? tb1 + unit * NV : eb2;

    // stage chunk 0
    {
        unsigned sb = (unsigned)__cvta_generic_to_shared(&Wbuf[0][0][0]);
        for (int i = t; i < KC * NV / 4; i += 256)
            cp16(sb + i * 16, Wg + i * 4);
        cp_commit();
    }

    int o0 = tx * 4;
    u64 acc[8][2];
    acc[0][0] = act ? pack2(bias[o0], bias[o0 + 1]) : 0ull;
    acc[0][1] = act ? pack2(bias[o0 + 2], bias[o0 + 3]) : 0ull;
#pragma unroll
    for (int i = 1; i < 8; i++) { acc[i][0] = acc[0][0]; acc[i][1] = acc[0][1]; }

    for (int c = 0; c < NCH; c++) {
        if (c + 1 < NCH) {
            unsigned sb = (unsigned)__cvta_generic_to_shared(&Wbuf[(c + 1) & 1][0][0]);
            const float* gsrc = Wg + (size_t)(c + 1) * KC * NV;
            for (int i = t; i < KC * NV / 4; i += 256)
                cp16(sb + i * 16, gsrc + i * 4);
            cp_commit();
            cp_wait<1>();
        } else {
            cp_wait<0>();
        }
        __syncthreads();
        if (act) {
            const float* Wb = &Wbuf[c & 1][0][0];
            int k0 = c * KC;
#pragma unroll
            for (int kc = 0; kc < KC; kc += 2) {
                ulonglong2 w0 = *(const ulonglong2*)(Wb + kc * NV + o0);
                ulonglong2 w1 = *(const ulonglong2*)(Wb + (kc + 1) * NV + o0);
#pragma unroll
                for (int i = 0; i < 8; i++) {
                    ulonglong2 x = *(const ulonglong2*)&Xd[ty * 8 + i][k0 + kc];
                    acc[i][0] = ffma2(x.x, w0.x, acc[i][0]);
                    acc[i][1] = ffma2(x.x, w0.y, acc[i][1]);
                    acc[i][0] = ffma2(x.y, w1.x, acc[i][0]);
                    acc[i][1] = ffma2(x.y, w1.y, acc[i][1]);
                }
            }
        }
        __syncthreads();   // protect Wbuf[c&1] before restage at c+2
    }

    // ---- epilogue: activation, *W2, reduce ----
    float p[8] = {0.f, 0.f, 0.f, 0.f, 0.f, 0.f, 0.f, 0.f};
    if (act) {
        float w2v[4];
#pragma unroll
        for (int j = 0; j < 4; j++)
            w2v[j] = (unit < 3) ? tW2[unit * NV + o0 + j] : eW3[o0 + j];
#pragma unroll
        for (int i = 0; i < 8; i++) {
            float2 v01 = unpack2(acc[i][0]);
            float2 v23 = unpack2(acc[i][1]);
            float v[4] = {v01.x, v01.y, v23.x, v23.y};
            float s = 0.f;
#pragma unroll
            for (int j = 0; j < 4; j++) {
                float x = v[j];
                x = (unit < 3) ? (x > 0.f ? x : expm1f(x)) : fmaxf(x, 0.f);
                s = fmaf(x, w2v[j], s);
            }
            p[i] = s;
        }
    }
    __syncthreads();                       // done reading Xd
    float* red = (float*)&Xd[0][0];        // red[50][33]
    if (act) {
#pragma unroll
        for (int i = 0; i < 8; i++) red[tx * 33 + ty * 8 + i] = p[i];
    }
    __syncthreads();
    if (t < BT) {
        float s = 0.f;
        for (int j = 0; j < 50; j++) s += red[j * 33 + t];
        float fb = (unit < 3) ? tb2[unit] : eb3[0];
        atomicAdd(&out[b0 + t], s + fb);
    }
}

// ---------------- launch ----------------
extern "C" void kernel_launch(void* const* d_in, const int* in_sizes, int n_in,
                              void* d_out, int out_size) {
    (void)in_sizes; (void)n_in; (void)out_size;
    const float* merged = (const float*)d_in[0];
    const float* a      = (const float*)d_in[1];
    const float* upWq   = (const float*)d_in[2];
    const float* upWk   = (const float*)d_in[3];
    const float* upWv   = (const float*)d_in[4];
    const float* dnWq   = (const float*)d_in[5];
    const float* dnWk   = (const float*)d_in[6];
    const float* dnWv   = (const float*)d_in[7];
    const float* pvWq   = (const float*)d_in[8];
    const float* pvWk   = (const float*)d_in[9];
    const float* pvWv   = (const float*)d_in[10];
    const float* tW1    = (const float*)d_in[11];
    const float* tb1    = (const float*)d_in[12];
    const float* tW2    = (const float*)d_in[13];
    const float* tb2    = (const float*)d_in[14];
    const float* eW1    = (const float*)d_in[15];
    const float* eb1    = (const float*)d_in[16];
    const float* eW2    = (const float*)d_in[17];
    const float* eb2    = (const float*)d_in[18];
    const float* eW3    = (const float*)d_in[19];
    const float* eb3    = (const float*)d_in[20];
    const float* gamma  = (const float*)d_in[21];
    const float* beta   = (const float*)d_in[22];
    float* out = (float*)d_out;

    k_attn<<<NB, 256>>>(merged, a, upWq, upWk, upWv, dnWq, dnWk, dnWv,
                        pvWq, pvWk, pvWv, out);
    k_stats<<<dim3(7, 3), dim3(32, 32)>>>();
    k_mlp<<<dim3(NB / BT, 4), 256>>>(merged, a, tW1, tb1, tW2, tb2,
                                     eW1, eb1, eW2, eb2, eW3, eb3,
                                     gamma, beta, out);
}